// round 3
// baseline (speedup 1.0000x reference)
#include <cuda_runtime.h>

namespace {
constexpr int PNP = 4;                 // num_pumps
constexpr int MOD = 4;                 // modes
constexpr int NCH = 100;               // num_channels
constexpr int F   = NCH + PNP;         // 104
constexpr int FM  = F * MOD;           // 416
constexpr int XW  = PNP * (1 + MOD);   // 20
constexpr int NT  = 128;
constexpr float C0F   = 299792458.0f;
constexpr float ALPHA = 2.3025850929940457e-4f;  // 1e-3*ln(10)/10
}

using ull = unsigned long long;

__device__ __forceinline__ ull pk2(float a, float b) {
    ull r; asm("mov.b64 %0,{%1,%2};" : "=l"(r) : "f"(a), "f"(b)); return r;
}
__device__ __forceinline__ void fma2(ull& d, ull a, ull b) {
    asm("fma.rn.f32x2 %0,%1,%2,%0;" : "+l"(d) : "l"(a), "l"(b));
}
__device__ __forceinline__ void add2(ull& d, ull a) {
    asm("add.rn.f32x2 %0,%0,%1;" : "+l"(d) : "l"(a));
}
__device__ __forceinline__ float2 up2(ull v) {
    float lo, hi; asm("mov.b64 {%0,%1},%2;" : "=f"(lo), "=f"(hi) : "l"(v));
    return make_float2(lo, hi);
}

// Q duplicated: Qd[8*j + 2m .. +1] = {Q[j][m], Q[j][m]}
#define DO_QCOMP()                                                       \
  for (int u = t; u < FM; u += NT) {                                     \
    const float4 pj = *(const float4*)(Pk + (u & ~3));                   \
    float qv = om0*pj.x + om1*pj.y + om2*pj.z + om3*pj.w;                \
    ((float2*)Qd)[u] = make_float2(qv, qv);                              \
  }                                                                      \
  __syncthreads();

// 4 rows (4r..4r+3) x 4 modes, 26 j's (this quarter's slice).
// A[m]   packs rows (4r,4r+1) mode m; A[4+m] packs rows (4r+2,4r+3).
#define DO_MATVEC(A)                                                     \
  ull A[8] = {0,0,0,0,0,0,0,0};                                          \
  if (r < 26) {                                                          \
    const int jb = qtr * 26;                                             \
    _Pragma("unroll 2")                                                  \
    for (int jj = 0; jj < 26; ++jj) {                                    \
      const int j = jb + jj;                                             \
      const float4 gv = *(const float4*)(gT + j * F + 4 * r);            \
      const ulonglong2 qa = *(const ulonglong2*)(Qd + 8 * j);            \
      const ulonglong2 qb = *(const ulonglong2*)(Qd + 8 * j + 4);        \
      const ull g01 = pk2(gv.x, gv.y);                                   \
      const ull g23 = pk2(gv.z, gv.w);                                   \
      fma2(A[0], g01, qa.x); fma2(A[1], g01, qa.y);                      \
      fma2(A[2], g01, qb.x); fma2(A[3], g01, qb.y);                      \
      fma2(A[4], g23, qa.x); fma2(A[5], g23, qa.y);                      \
      fma2(A[6], g23, qb.x); fma2(A[7], g23, qb.y);                      \
    }                                                                    \
  }

// quarters 1..3 publish partials; quarter 0 reduces and gets 16 sums
#define DO_REDUCE(A, sums)                                               \
  if (qtr != 0 && r < 26) {                                              \
    ulonglong2* rp = (ulonglong2*)red + ((qtr - 1) * 26 + r) * 4;        \
    rp[0] = make_ulonglong2(A[0], A[1]);                                 \
    rp[1] = make_ulonglong2(A[2], A[3]);                                 \
    rp[2] = make_ulonglong2(A[4], A[5]);                                 \
    rp[3] = make_ulonglong2(A[6], A[7]);                                 \
  }                                                                      \
  __syncthreads();                                                       \
  float sums[16];                                                        \
  if (qtr == 0 && r < 26) {                                              \
    _Pragma("unroll")                                                    \
    for (int p = 0; p < 3; ++p) {                                        \
      const ulonglong2* rp = (const ulonglong2*)red + (p * 26 + r) * 4;  \
      ulonglong2 v0 = rp[0], v1 = rp[1], v2 = rp[2], v3 = rp[3];         \
      add2(A[0], v0.x); add2(A[1], v0.y);                                \
      add2(A[2], v1.x); add2(A[3], v1.y);                                \
      add2(A[4], v2.x); add2(A[5], v2.y);                                \
      add2(A[6], v3.x); add2(A[7], v3.y);                                \
    }                                                                    \
    _Pragma("unroll")                                                    \
    for (int m = 0; m < 4; ++m) {                                        \
      float2 v0 = up2(A[m]);     sums[m]      = v0.x; sums[4 + m]  = v0.y; \
      float2 v1 = up2(A[4 + m]); sums[8 + m]  = v1.x; sums[12 + m] = v1.y; \
    }                                                                    \
  }

__global__ __launch_bounds__(NT, 4) void raman_kernel(
    const float* __restrict__ x,
    const float* __restrict__ sig_freq,
    const float* __restrict__ sig_pow,
    const float* __restrict__ sig_loss,
    const float* __restrict__ lcoef,
    const float* __restrict__ overlap,
    const float* __restrict__ raman,
    const int*   __restrict__ steps_p,
    const float* __restrict__ length_p,
    const float* __restrict__ maxf_p,
    int Lr,
    float* __restrict__ out)
{
    extern __shared__ float sm[];
    float* gT  = sm;               // F*F floats: gT[j*F+i] = gain[i][j]
    float* Qd  = gT + F * F;       // 2*FM (Q duplicated pairs)
    float* Pc  = Qd + 2 * FM;      // FM
    float* Pk  = Pc + FM;          // FM
    float* accv= Pk + FM;          // FM
    float* red = accv + FM;        // 3*26*16 = 1248 floats
    float* freqs = red;            // alias (init phase only)

    const int b = blockIdx.x;
    const int t = threadIdx.x;
    const int qtr = t >> 5;
    const int r   = t & 31;
    const float* xb = x + b * XW;

    const int   steps  = *steps_p;
    const float length = *length_p;
    const float maxf   = *maxf_p;
    const float h  = length / (float)(steps - 1);
    const float h2 = 0.5f * h;
    const float h6 = h * (1.0f / 6.0f);

    // overlap row for this thread's mode (u&3 == t&3 for stride-NT loops)
    const float om0 = overlap[(t & 3) * 4 + 0];
    const float om1 = overlap[(t & 3) * 4 + 1];
    const float om2 = overlap[(t & 3) * 4 + 2];
    const float om3 = overlap[(t & 3) * 4 + 3];

    for (int u = t; u < F; u += NT)
        freqs[u] = (u < PNP) ? (C0F / xb[u]) : sig_freq[u - PNP];
    for (int u = t; u < FM; u += NT) {
        float pv = (u < PNP * MOD) ? xb[PNP + u] : sig_pow[u - PNP * MOD];
        Pc[u] = pv; Pk[u] = pv;
    }
    __syncthreads();

    // ---- per-batch 104x104 gain matrix, transposed ----
    {
        const float scale = (float)(Lr - 1) / maxf;
        for (int idx = t; idx < F * F; idx += NT) {
            const int jj = idx / F;          // column j (contiguous store)
            const int ii = idx - jj * F;     // row i
            const float fi = freqs[ii], fj = freqs[jj];
            const float fd = fj - fi;
            const float pos = fabsf(fd) * scale;
            int i0 = (int)floorf(pos);
            i0 = min(max(i0, 0), Lr - 2);
            const float w = pos - (float)i0;
            float g = raman[i0] * (1.0f - w) + raman[i0 + 1] * w;
            if (fd < 0.0f) g = -g;
            g *= fmaxf(1.0f, fi / fj);
            gT[idx] = g;
        }
    }

    // losses for the 16 entries this quarter-0 thread updates
    float ls[16];
    const bool upd = (qtr == 0 && r < 26);
    if (upd) {
        const float lc0 = lcoef[0], lc1 = lcoef[1], lc2 = lcoef[2];
        #pragma unroll
        for (int le = 0; le < 16; ++le) {
            const int u = 16 * r + le;
            const int row = u >> 2;
            if (row < PNP) {
                const float wn = xb[row] * 1e9f;
                ls[le] = (lc2 + lc1 * wn + lc0 * wn * wn) * ALPHA;
            } else {
                ls[le] = sig_loss[u - PNP * MOD];
            }
        }
    }
    __syncthreads();

    float4* Pc4 = (float4*)(Pc + 16 * r);
    float4* Pk4 = (float4*)(Pk + 16 * r);
    float4* ac4 = (float4*)(accv + 16 * r);

    for (int s = 0; s < steps - 1; ++s) {
        {   // stage 1: k1
            DO_QCOMP();
            DO_MATVEC(A);
            DO_REDUCE(A, sums);
            if (upd) {
                #pragma unroll
                for (int w4 = 0; w4 < 4; ++w4) {
                    float4 pc = Pc4[w4], pk = Pk4[w4];
                    float4 k4;
                    k4.x = (sums[4*w4+0] - ls[4*w4+0]) * pk.x;
                    k4.y = (sums[4*w4+1] - ls[4*w4+1]) * pk.y;
                    k4.z = (sums[4*w4+2] - ls[4*w4+2]) * pk.z;
                    k4.w = (sums[4*w4+3] - ls[4*w4+3]) * pk.w;
                    ac4[w4] = k4;
                    Pk4[w4] = make_float4(fmaf(h2,k4.x,pc.x), fmaf(h2,k4.y,pc.y),
                                          fmaf(h2,k4.z,pc.z), fmaf(h2,k4.w,pc.w));
                }
            }
            __syncthreads();
        }
        {   // stage 2: k2
            DO_QCOMP();
            DO_MATVEC(A);
            DO_REDUCE(A, sums);
            if (upd) {
                #pragma unroll
                for (int w4 = 0; w4 < 4; ++w4) {
                    float4 pc = Pc4[w4], pk = Pk4[w4], av = ac4[w4];
                    float4 k4;
                    k4.x = (sums[4*w4+0] - ls[4*w4+0]) * pk.x;
                    k4.y = (sums[4*w4+1] - ls[4*w4+1]) * pk.y;
                    k4.z = (sums[4*w4+2] - ls[4*w4+2]) * pk.z;
                    k4.w = (sums[4*w4+3] - ls[4*w4+3]) * pk.w;
                    ac4[w4] = make_float4(av.x + 2.f*k4.x, av.y + 2.f*k4.y,
                                          av.z + 2.f*k4.z, av.w + 2.f*k4.w);
                    Pk4[w4] = make_float4(fmaf(h2,k4.x,pc.x), fmaf(h2,k4.y,pc.y),
                                          fmaf(h2,k4.z,pc.z), fmaf(h2,k4.w,pc.w));
                }
            }
            __syncthreads();
        }
        {   // stage 3: k3
            DO_QCOMP();
            DO_MATVEC(A);
            DO_REDUCE(A, sums);
            if (upd) {
                #pragma unroll
                for (int w4 = 0; w4 < 4; ++w4) {
                    float4 pc = Pc4[w4], pk = Pk4[w4], av = ac4[w4];
                    float4 k4;
                    k4.x = (sums[4*w4+0] - ls[4*w4+0]) * pk.x;
                    k4.y = (sums[4*w4+1] - ls[4*w4+1]) * pk.y;
                    k4.z = (sums[4*w4+2] - ls[4*w4+2]) * pk.z;
                    k4.w = (sums[4*w4+3] - ls[4*w4+3]) * pk.w;
                    ac4[w4] = make_float4(av.x + 2.f*k4.x, av.y + 2.f*k4.y,
                                          av.z + 2.f*k4.z, av.w + 2.f*k4.w);
                    Pk4[w4] = make_float4(fmaf(h,k4.x,pc.x), fmaf(h,k4.y,pc.y),
                                          fmaf(h,k4.z,pc.z), fmaf(h,k4.w,pc.w));
                }
            }
            __syncthreads();
        }
        {   // stage 4: k4 + combine
            DO_QCOMP();
            DO_MATVEC(A);
            DO_REDUCE(A, sums);
            if (upd) {
                #pragma unroll
                for (int w4 = 0; w4 < 4; ++w4) {
                    float4 pc = Pc4[w4], pk = Pk4[w4], av = ac4[w4];
                    float4 k4;
                    k4.x = (sums[4*w4+0] - ls[4*w4+0]) * pk.x;
                    k4.y = (sums[4*w4+1] - ls[4*w4+1]) * pk.y;
                    k4.z = (sums[4*w4+2] - ls[4*w4+2]) * pk.z;
                    k4.w = (sums[4*w4+3] - ls[4*w4+3]) * pk.w;
                    float4 np;
                    np.x = fmaf(h6, av.x + k4.x, pc.x);
                    np.y = fmaf(h6, av.y + k4.y, pc.y);
                    np.z = fmaf(h6, av.z + k4.z, pc.z);
                    np.w = fmaf(h6, av.w + k4.w, pc.w);
                    Pc4[w4] = np; Pk4[w4] = np;
                }
            }
            __syncthreads();
        }
    }

    // output: (B, NCH, MOD), drop pump rows
    for (int u = t; u < NCH * MOD; u += NT)
        out[b * (NCH * MOD) + u] = Pc[PNP * MOD + u];
}

extern "C" void kernel_launch(void* const* d_in, const int* in_sizes, int n_in,
                              void* d_out, int out_size) {
    const float* x        = (const float*)d_in[0];
    const float* sig_freq = (const float*)d_in[1];
    const float* sig_pow  = (const float*)d_in[2];
    const float* sig_loss = (const float*)d_in[3];
    const float* lcoef    = (const float*)d_in[4];
    const float* overlap  = (const float*)d_in[5];
    const float* raman    = (const float*)d_in[6];
    const int*   steps_p  = (const int*)d_in[10];
    const float* length_p = (const float*)d_in[11];
    const float* maxf_p   = (const float*)d_in[12];

    const int B  = in_sizes[0] / XW;
    const int Lr = in_sizes[6];

    // gT + Qd(dup) + Pc + Pk + acc + red
    const size_t smem = (size_t)(F*F + 2*FM + 3*FM + 3*26*16) * sizeof(float); // 56576 B
    cudaFuncSetAttribute(raman_kernel,
                         cudaFuncAttributeMaxDynamicSharedMemorySize, (int)smem);

    raman_kernel<<<B, NT, smem>>>(x, sig_freq, sig_pow, sig_loss, lcoef, overlap,
                                  raman, steps_p, length_p, maxf_p, Lr,
                                  (float*)d_out);
}

// round 4
// speedup vs baseline: 1.5988x; 1.5988x over previous
#include <cuda_runtime.h>

namespace {
constexpr int PNP = 4;
constexpr int MOD = 4;
constexpr int NCH = 100;
constexpr int F   = NCH + PNP;       // 104
constexpr int FM  = F * MOD;         // 416
constexpr int XW  = PNP * (1 + MOD); // 20
constexpr int NT  = 128;
constexpr float C0F   = 299792458.0f;
constexpr float ALPHA = 2.3025850929940457e-4f;
}

using ull = unsigned long long;

__device__ __forceinline__ ull pk2(float a, float b) {
    ull r; asm("mov.b64 %0,{%1,%2};" : "=l"(r) : "f"(a), "f"(b)); return r;
}
__device__ __forceinline__ void fma2(ull& d, ull a, ull b) {
    asm("fma.rn.f32x2 %0,%1,%2,%0;" : "+l"(d) : "l"(a), "l"(b));
}
__device__ __forceinline__ float2 up2(ull v) {
    float lo, hi; asm("mov.b64 {%0,%1},%2;" : "=f"(lo), "=f"(hi) : "l"(v));
    return make_float2(lo, hi);
}

__global__ __launch_bounds__(NT, 4) void raman_kernel(
    const float* __restrict__ x,
    const float* __restrict__ sig_freq,
    const float* __restrict__ sig_pow,
    const float* __restrict__ sig_loss,
    const float* __restrict__ lcoef,
    const float* __restrict__ overlap,
    const float* __restrict__ raman,
    const int*   __restrict__ steps_p,
    const float* __restrict__ length_p,
    const float* __restrict__ maxf_p,
    int Lr,
    float* __restrict__ out)
{
    extern __shared__ float sm[];
    float* gT  = sm;              // F*F, row-major gain[i][j] (init only; reg-loaded)
    float* Qb  = gT + F * F;      // 2 * FM (double-buffered Q, 16B aligned)
    float* PcS = Qb + 2 * FM;     // FM (step-start state)
    float* ovS = PcS + FM;        // 16: ovS[mj*4+m] = overlap[m][mj]
    float* frq = ovS + 16;        // F

    const int b = blockIdx.x;
    const int t = threadIdx.x;
    const float* xb = x + b * XW;

    const int   steps  = *steps_p;
    const float length = *length_p;
    const float maxf   = *maxf_p;
    const float h  = length / (float)(steps - 1);
    const float h2 = 0.5f * h;
    const float h6 = h * (1.0f / 6.0f);

    for (int u = t; u < F; u += NT)
        frq[u] = (u < PNP) ? (C0F / xb[u]) : sig_freq[u - PNP];
    if (t < 16) ovS[t] = overlap[(t & 3) * 4 + (t >> 2)];  // transposed (symmetric anyway)
    __syncthreads();

    // ---- per-batch gain matrix into smem (transient), row-major ----
    {
        const float scale = (float)(Lr - 1) / maxf;
        for (int idx = t; idx < F * F; idx += NT) {
            const int ii = idx / F;
            const int jj = idx - ii * F;
            const float fi = frq[ii], fj = frq[jj];
            const float fd = fj - fi;
            const float pos = fabsf(fd) * scale;
            int i0 = (int)floorf(pos);
            i0 = min(max(i0, 0), Lr - 2);
            const float w = pos - (float)i0;
            float g = raman[i0] * (1.0f - w) + raman[i0 + 1] * w;
            if (fd < 0.0f) g = -g;
            g *= fmaxf(1.0f, fi / fj);
            gT[idx] = g;
        }
    }
    __syncthreads();

    const int  i     = t;
    const bool rowok = (i < F);

    // ---- own gain row -> registers (persistent across all stages) ----
    float gain[F];
    if (rowok) {
        #pragma unroll
        for (int j = 0; j < F; ++j) gain[j] = gT[i * F + j];
    }

    // ---- per-row loss + initial power (registers) ----
    float l0 = 0.f, l1 = 0.f, l2 = 0.f, l3 = 0.f;
    float pk0 = 0.f, pk1 = 0.f, pk2v = 0.f, pk3 = 0.f;
    if (rowok) {
        if (i < PNP) {
            const float wn = xb[i] * 1e9f;
            const float lv = (lcoef[2] + lcoef[1] * wn + lcoef[0] * wn * wn) * ALPHA;
            l0 = l1 = l2 = l3 = lv;
            pk0 = xb[PNP + 4 * i + 0];
            pk1 = xb[PNP + 4 * i + 1];
            pk2v = xb[PNP + 4 * i + 2];
            pk3 = xb[PNP + 4 * i + 3];
        } else {
            const int u = 4 * i - PNP * MOD;
            l0 = sig_loss[u + 0]; l1 = sig_loss[u + 1];
            l2 = sig_loss[u + 2]; l3 = sig_loss[u + 3];
            pk0 = sig_pow[u + 0]; pk1 = sig_pow[u + 1];
            pk2v = sig_pow[u + 2]; pk3 = sig_pow[u + 3];
        }
        *(float4*)(PcS + 4 * i) = make_float4(pk0, pk1, pk2v, pk3);
        // prologue Q(P0) into buffer 0
        ull q01 = 0, q23 = 0;
        #pragma unroll
        for (int mj = 0; mj < 4; ++mj) {
            const ulonglong2 ov2 = ((const ulonglong2*)ovS)[mj];
            const float pm = (mj == 0) ? pk0 : (mj == 1) ? pk1 : (mj == 2) ? pk2v : pk3;
            const ull pp = pk2(pm, pm);
            fma2(q01, ov2.x, pp); fma2(q23, ov2.y, pp);
        }
        ((ulonglong2*)Qb)[i] = make_ulonglong2(q01, q23);
    }
    __syncthreads();

    float ac0 = 0.f, ac1 = 0.f, ac2 = 0.f, ac3 = 0.f;
    const int nst = 4 * (steps - 1);
    int cur = 0;

    for (int it = 0; it < nst; ++it) {
        const int s4 = it & 3;
        if (rowok) {
            // ---- matvec: a[m] = sum_j gain[j] * Q[j][m] ----
            ull a01 = 0, a23 = 0;
            const ulonglong2* Qc = (const ulonglong2*)(Qb + cur * FM);
            #pragma unroll
            for (int j = 0; j < F; ++j) {
                const ulonglong2 q = Qc[j];
                const ull gg = pk2(gain[j], gain[j]);
                fma2(a01, gg, q.x); fma2(a23, gg, q.y);
            }
            const float2 s01 = up2(a01), s23 = up2(a23);
            const float k0 = (s01.x - l0) * pk0;
            const float k1 = (s01.y - l1) * pk1;
            const float k2 = (s23.x - l2) * pk2v;
            const float k3 = (s23.y - l3) * pk3;

            const float4 pc = *(const float4*)(PcS + 4 * i);
            if (s4 == 0)      { ac0 = k0; ac1 = k1; ac2 = k2; ac3 = k3; }
            else if (s4 < 3)  { ac0 += 2.f * k0; ac1 += 2.f * k1;
                                ac2 += 2.f * k2; ac3 += 2.f * k3; }
            else              { ac0 += k0; ac1 += k1; ac2 += k2; ac3 += k3; }

            if (s4 < 3) {
                const float cs = (s4 == 2) ? h : h2;
                pk0 = fmaf(cs, k0, pc.x);
                pk1 = fmaf(cs, k1, pc.y);
                pk2v = fmaf(cs, k2, pc.z);
                pk3 = fmaf(cs, k3, pc.w);
            } else {
                pk0 = fmaf(h6, ac0, pc.x);
                pk1 = fmaf(h6, ac1, pc.y);
                pk2v = fmaf(h6, ac2, pc.z);
                pk3 = fmaf(h6, ac3, pc.w);
                *(float4*)(PcS + 4 * i) = make_float4(pk0, pk1, pk2v, pk3);
            }

            // ---- Q for next stage into alternate buffer ----
            ull q01 = 0, q23 = 0;
            #pragma unroll
            for (int mj = 0; mj < 4; ++mj) {
                const ulonglong2 ov2 = ((const ulonglong2*)ovS)[mj];
                const float pm = (mj == 0) ? pk0 : (mj == 1) ? pk1 : (mj == 2) ? pk2v : pk3;
                const ull pp = pk2(pm, pm);
                fma2(q01, ov2.x, pp); fma2(q23, ov2.y, pp);
            }
            ((ulonglong2*)(Qb + (cur ^ 1) * FM))[i] = make_ulonglong2(q01, q23);
        }
        __syncthreads();
        cur ^= 1;
    }

    if (rowok && i >= PNP)
        *(float4*)(out + b * (NCH * MOD) + (i - PNP) * 4) =
            make_float4(pk0, pk1, pk2v, pk3);
}

extern "C" void kernel_launch(void* const* d_in, const int* in_sizes, int n_in,
                              void* d_out, int out_size) {
    const float* x        = (const float*)d_in[0];
    const float* sig_freq = (const float*)d_in[1];
    const float* sig_pow  = (const float*)d_in[2];
    const float* sig_loss = (const float*)d_in[3];
    const float* lcoef    = (const float*)d_in[4];
    const float* overlap  = (const float*)d_in[5];
    const float* raman    = (const float*)d_in[6];
    const int*   steps_p  = (const int*)d_in[10];
    const float* length_p = (const float*)d_in[11];
    const float* maxf_p   = (const float*)d_in[12];

    const int B  = in_sizes[0] / XW;
    const int Lr = in_sizes[6];

    const size_t smem = (size_t)(F*F + 2*FM + FM + 16 + F) * sizeof(float); // 48736 B
    cudaFuncSetAttribute(raman_kernel,
                         cudaFuncAttributeMaxDynamicSharedMemorySize, (int)smem);

    raman_kernel<<<B, NT, smem>>>(x, sig_freq, sig_pow, sig_loss, lcoef, overlap,
                                  raman, steps_p, length_p, maxf_p, Lr,
                                  (float*)d_out);
}